// round 17
// baseline (speedup 1.0000x reference)
#include <cuda_runtime.h>
#include <cstdint>
#include <math.h>

#define S_SEG 256
#define T_TOK 512
#define BERT  768
#define POSD  128
#define CAT   (BERT + POSD)   // 896
#define H1    1024
#define NCLS  6
#define NSEG  64
#define KSLICES 32
#define TOKW    32                       // tokens per warp
#define WSLICES (T_TOK / TOKW)           // 16 warp-slices per segment

// Scratch (no allocations allowed) — device globals.
__device__ float g_pacc[WSLICES * S_SEG * BERT];   // unnormalized partial accumulators
__device__ float g_pd[WSLICES * S_SEG];            // partial denom
__device__ float g_vecs[NSEG * BERT];
__device__ float g_h1[NSEG * H1];
__device__ float g_part[KSLICES * NSEG * H1];

#define CP_ASYNC_16(dst_u32, src_ptr) \
    asm volatile("cp.async.cg.shared.global [%0], [%1], 16;" \
                 :: "r"(dst_u32), "l"(src_ptr) : "memory")
#define CP_ASYNC_WAIT_ALL() \
    asm volatile("cp.async.commit_group;\n\tcp.async.wait_group 0;" ::: "memory")

// ---------------------------------------------------------------------------
// Kernel 1: warp-per-token softmax pooling (direct exp — logits O(1)).
// TWO tokens per iteration; __ldcs streaming loads (zero-reuse data).
// grid (256, 4) x 128 threads = 1024 CTAs, warp (s, q*4+wid) does 32 tokens.
// ---------------------------------------------------------------------------
__global__ __launch_bounds__(128, 5)
void pool_part_kernel(const float* __restrict__ emb,
                      const float* __restrict__ pos,
                      const float* __restrict__ Wa,
                      const float* __restrict__ ba)
{
    __shared__ float s_wa[CAT];
    const int s    = blockIdx.x;
    const int q    = blockIdx.y;
    const int tid  = threadIdx.x;
    const int wid  = tid >> 5;
    const int lane = tid & 31;

    for (int i = tid; i < CAT; i += 128) s_wa[i] = Wa[i];
    __syncthreads();   // only barrier in the kernel

    const int   slice = q * 4 + wid;
    const int   t0    = slice * TOKW;
    const float bias  = ba[0];

    const float* eb = emb + (size_t)s * T_TOK * BERT;
    const float* pb = pos + (size_t)s * T_TOK * POSD;

    float4 acc[6];
    #pragma unroll
    for (int i = 0; i < 6; i++) acc[i] = make_float4(0.f, 0.f, 0.f, 0.f);
    float d = 0.f;

    #pragma unroll 1
    for (int j = 0; j < TOKW; j += 2) {
        const int t = t0 + j;

        float4 x0[7], x1[7];
        #pragma unroll
        for (int i = 0; i < 6; i++)
            x0[i] = __ldcs((const float4*)(eb + (size_t)t * BERT + i * 128 + lane * 4));
        x0[6] = __ldcs((const float4*)(pb + (size_t)t * POSD + lane * 4));
        #pragma unroll
        for (int i = 0; i < 6; i++)
            x1[i] = __ldcs((const float4*)(eb + (size_t)(t + 1) * BERT + i * 128 + lane * 4));
        x1[6] = __ldcs((const float4*)(pb + (size_t)(t + 1) * POSD + lane * 4));

        float p0 = 0.f, p1 = 0.f;
        #pragma unroll
        for (int i = 0; i < 7; i++) {
            const float4 wv = *(const float4*)(s_wa + i * 128 + lane * 4);
            p0 += x0[i].x * wv.x + x0[i].y * wv.y + x0[i].z * wv.z + x0[i].w * wv.w;
            p1 += x1[i].x * wv.x + x1[i].y * wv.y + x1[i].z * wv.z + x1[i].w * wv.w;
        }
        #pragma unroll
        for (int o = 16; o > 0; o >>= 1) {
            p0 += __shfl_xor_sync(0xffffffffu, p0, o);
            p1 += __shfl_xor_sync(0xffffffffu, p1, o);
        }

        const float e0 = __expf(p0 + bias);
        const float e1 = __expf(p1 + bias);
        d += e0 + e1;
        #pragma unroll
        for (int i = 0; i < 6; i++) {
            acc[i].x += e0 * x0[i].x + e1 * x1[i].x;
            acc[i].y += e0 * x0[i].y + e1 * x1[i].y;
            acc[i].z += e0 * x0[i].z + e1 * x1[i].z;
            acc[i].w += e0 * x0[i].w + e1 * x1[i].w;
        }
    }

    const int ps = slice * S_SEG + s;
    float* ob = g_pacc + (size_t)ps * BERT;
    #pragma unroll
    for (int i = 0; i < 6; i++)
        *(float4*)(ob + i * 128 + lane * 4) = acc[i];
    if (lane == 0) g_pd[ps] = d;
}

// ---------------------------------------------------------------------------
// Kernel 2: FUSED merge + segment-sum. grid 64 (comment groups), 192 threads
// (one float4 of 768 channels each). For each segment s with sid[s]==g:
// vecs[g] += (sum_z pacc[z,s]) / (sum_z pd[z,s]). Sorted ids -> exact match
// with reference segment_sum. Eliminates the segvec round trip.
// ---------------------------------------------------------------------------
__global__ __launch_bounds__(192)
void merge_segsum_kernel(const int* __restrict__ seg)
{
    __shared__ int   sid[S_SEG];
    __shared__ float spd[WSLICES * S_SEG];   // 16KB
    const int g   = blockIdx.x;
    const int tid = threadIdx.x;

    for (int i = tid; i < S_SEG; i += 192) sid[i] = seg[i];
    for (int i = tid; i < WSLICES * S_SEG; i += 192) spd[i] = g_pd[i];
    __syncthreads();

    const int c4 = tid * 4;
    float4 out = make_float4(0.f, 0.f, 0.f, 0.f);

    #pragma unroll 1
    for (int s = 0; s < S_SEG; s++) {
        if (sid[s] != g) continue;
        float D = 0.f;
        #pragma unroll
        for (int z = 0; z < WSLICES; z++) D += spd[z * S_SEG + s];
        const float inv = 1.f / D;

        float4 acc = make_float4(0.f, 0.f, 0.f, 0.f);
        #pragma unroll
        for (int z = 0; z < WSLICES; z++) {
            const float4 p = *(const float4*)(g_pacc + (size_t)(z * S_SEG + s) * BERT + c4);
            acc.x += p.x; acc.y += p.y; acc.z += p.z; acc.w += p.w;
        }
        out.x += acc.x * inv;
        out.y += acc.y * inv;
        out.z += acc.z * inv;
        out.w += acc.w * inv;
    }

    *(float4*)(g_vecs + (size_t)g * BERT + c4) = out;
}

// ---------------------------------------------------------------------------
// Kernels 3/5: split-K GEMM partials, cp.async-staged smem tiles.
// grid (16 colblocks, KSLICES=32) = 512 CTAs, 256 threads.
// CTA = ALL 64 rows x 64 cols x CHUNK — W tile staged ONCE per CTA.
// ---------------------------------------------------------------------------
template <int K>
__global__ __launch_bounds__(256)
void mlp_splitk_kernel(const float* __restrict__ in, const float* __restrict__ W,
                       float* __restrict__ part)
{
    constexpr int CHUNK = K / KSLICES;   // 24 or 32
    constexpr int C4    = CHUNK / 4;
    __shared__ float ws[CHUNK * 64];     // W tile [kk][64]
    __shared__ float xs[64 * CHUNK];     // x tile [row][kk]

    const int tid   = threadIdx.x;
    const int q     = tid & 15;
    const int r     = tid >> 4;          // 0..15
    const int jbase = blockIdx.x * 64 + q * 4;
    const int k0    = blockIdx.y * CHUNK;

    const uint32_t ws_u = (uint32_t)__cvta_generic_to_shared(ws);
    const uint32_t xs_u = (uint32_t)__cvta_generic_to_shared(xs);

    const float* wg = W + (size_t)k0 * H1 + blockIdx.x * 64;
    #pragma unroll
    for (int idx = tid; idx < CHUNK * 16; idx += 256) {
        const int kk = idx >> 4;
        const int cc = idx & 15;
        CP_ASYNC_16(ws_u + (uint32_t)(kk * 64 + cc * 4) * 4,
                    wg + (size_t)kk * H1 + cc * 4);
    }
    const float* xg = in + k0;
    #pragma unroll
    for (int idx = tid; idx < 64 * C4; idx += 256) {
        const int rr = idx / C4;
        const int cc = idx - rr * C4;
        CP_ASYNC_16(xs_u + (uint32_t)(rr * CHUNK + cc * 4) * 4,
                    xg + (size_t)rr * K + cc * 4);
    }
    CP_ASYNC_WAIT_ALL();
    __syncthreads();

    float4 acc[4];
    #pragma unroll
    for (int i = 0; i < 4; i++) acc[i] = make_float4(0.f, 0.f, 0.f, 0.f);

    const float* xp = xs + (r * 4) * CHUNK;

    #pragma unroll 8
    for (int kk = 0; kk < CHUNK; kk++) {
        const float4 wv = *(const float4*)(ws + kk * 64 + q * 4);
        #pragma unroll
        for (int rr = 0; rr < 4; rr++) {
            const float xv = xp[rr * CHUNK + kk];
            acc[rr].x += xv * wv.x;
            acc[rr].y += xv * wv.y;
            acc[rr].z += xv * wv.z;
            acc[rr].w += xv * wv.w;
        }
    }

    float* pb = part + (size_t)blockIdx.y * NSEG * H1 + (size_t)(r * 4) * H1 + jbase;
    #pragma unroll
    for (int i = 0; i < 4; i++)
        *(float4*)(pb + (size_t)i * H1) = acc[i];
}

// Kernel 4: reduce partials + bias + LeakyReLU(0.01) for layer 1.
__global__ __launch_bounds__(256)
void mlp_reduce_kernel(const float* __restrict__ b, float* __restrict__ out)
{
    const int row = blockIdx.x >> 2;
    const int col = (blockIdx.x & 3) * 256 + threadIdx.x;
    const size_t off = (size_t)row * H1 + col;

    float a = 0.f;
    #pragma unroll
    for (int z = 0; z < KSLICES; z++)
        a += g_part[(size_t)z * NSEG * H1 + off];

    a += b[col];
    out[off] = a > 0.f ? a : 0.01f * a;
}

// ---------------------------------------------------------------------------
// Kernel 6: FUSED reduce2 + head. grid 64 (groups), 256 threads.
// Thread t sums 32 g_part slices for cols t*4..t*4+3, applies b2+LeakyReLU,
// dots with W3, block-reduces 6 accumulators, sigmoid, writes out[g].
// ---------------------------------------------------------------------------
__global__ __launch_bounds__(256)
void head_fused_kernel(const float* __restrict__ b2,
                       const float* __restrict__ W3,
                       const float* __restrict__ b3,
                       float* __restrict__ out)
{
    __shared__ float sred[8][NCLS];
    const int g    = blockIdx.x;
    const int tid  = threadIdx.x;
    const int wid  = tid >> 5;
    const int lane = tid & 31;
    const int c4   = tid * 4;

    float4 a = make_float4(0.f, 0.f, 0.f, 0.f);
    #pragma unroll
    for (int z = 0; z < KSLICES; z++) {
        const float4 p = *(const float4*)(g_part + (size_t)z * NSEG * H1 + (size_t)g * H1 + c4);
        a.x += p.x; a.y += p.y; a.z += p.z; a.w += p.w;
    }
    const float4 bb = *(const float4*)(b2 + c4);
    float h[4];
    h[0] = a.x + bb.x; h[0] = h[0] > 0.f ? h[0] : 0.01f * h[0];
    h[1] = a.y + bb.y; h[1] = h[1] > 0.f ? h[1] : 0.01f * h[1];
    h[2] = a.z + bb.z; h[2] = h[2] > 0.f ? h[2] : 0.01f * h[2];
    h[3] = a.w + bb.w; h[3] = h[3] > 0.f ? h[3] : 0.01f * h[3];

    float p[NCLS] = {0.f, 0.f, 0.f, 0.f, 0.f, 0.f};
    #pragma unroll
    for (int c = 0; c < 4; c++) {
        const float* w3 = W3 + (size_t)(c4 + c) * NCLS;
        #pragma unroll
        for (int j = 0; j < NCLS; j++)
            p[j] += h[c] * w3[j];
    }
    #pragma unroll
    for (int j = 0; j < NCLS; j++) {
        #pragma unroll
        for (int o = 16; o > 0; o >>= 1)
            p[j] += __shfl_xor_sync(0xffffffffu, p[j], o);
    }
    if (lane == 0) {
        #pragma unroll
        for (int j = 0; j < NCLS; j++) sred[wid][j] = p[j];
    }
    __syncthreads();
    if (tid < NCLS) {
        float v = b3[tid];
        #pragma unroll
        for (int w = 0; w < 8; w++) v += sred[w][tid];
        out[g * NCLS + tid] = 1.f / (1.f + expf(-v));
    }
}

// ---------------------------------------------------------------------------
extern "C" void kernel_launch(void* const* d_in, const int* in_sizes, int n_in,
                              void* d_out, int out_size)
{
    (void)in_sizes; (void)n_in; (void)out_size;
    const float* emb = (const float*)d_in[0];
    const float* pos = (const float*)d_in[1];
    const float* Wa  = (const float*)d_in[2];
    const float* ba  = (const float*)d_in[3];
    const float* W1  = (const float*)d_in[4];
    const float* b1  = (const float*)d_in[5];
    const float* W2  = (const float*)d_in[6];
    const float* b2  = (const float*)d_in[7];
    const float* W3  = (const float*)d_in[8];
    const float* b3  = (const float*)d_in[9];
    const int*   seg = (const int*)d_in[10];
    float* out = (float*)d_out;

    void *p_vecs = nullptr, *p_h1 = nullptr, *p_part = nullptr;
    cudaGetSymbolAddress(&p_vecs, g_vecs);
    cudaGetSymbolAddress(&p_h1, g_h1);
    cudaGetSymbolAddress(&p_part, g_part);

    pool_part_kernel<<<dim3(S_SEG, 4), 128>>>(emb, pos, Wa, ba);
    merge_segsum_kernel<<<NSEG, 192>>>(seg);

    mlp_splitk_kernel<BERT><<<dim3(16, KSLICES), 256>>>(
        (const float*)p_vecs, W1, (float*)p_part);
    mlp_reduce_kernel<<<NSEG * 4, 256>>>(b1, (float*)p_h1);

    mlp_splitk_kernel<H1><<<dim3(16, KSLICES), 256>>>(
        (const float*)p_h1, W2, (float*)p_part);
    head_fused_kernel<<<NSEG, 256>>>(b2, W3, b3, out);
}